// round 1
// baseline (speedup 1.0000x reference)
#include <cuda_runtime.h>
#include <cstdint>

#define NN 8192      // nodes
#define DF 128       // feature dim
#define NA 512       // anchors
#define KSEL 32      // k nearest
#define MARGINF 1.0f

// distance-kernel tiling
#define TA 32        // anchors per CTA
#define TN 64        // nodes per CTA
#define RA 4         // anchors per thread
#define RN 2         // nodes per thread
#define SROW 132     // padded smem row stride (words); 132*4=528 is 16B-aligned, 132%32=4 -> conflict-free LDS.128

// scratch (device globals: allocation-free)
__device__ __align__(16) float g_ga[2][NA][DF];     // gathered anchor rows
__device__ float g_D[NA];                            // rowdist(a1,a2)+margin
__device__ float g_dist[2][NA][NN];                  // full distance matrices (32 MB)
__device__ float g_rowLoss[2 * NA];

// ---------------------------------------------------------------------------
// Kernel 1: gather anchor rows + compute D[a] = L1(a1[a], a2[a]) + margin
// ---------------------------------------------------------------------------
__global__ void k_gather(const float* __restrict__ out1, const float* __restrict__ out2,
                         const int* __restrict__ an1, const int* __restrict__ an2) {
    int a = blockIdx.x, t = threadIdx.x;
    int i1 = an1[a], i2 = an2[a];
    float v1 = out1[(size_t)i1 * DF + t];
    float v2 = out2[(size_t)i2 * DF + t];
    g_ga[0][a][t] = v1;
    g_ga[1][a][t] = v2;
    __shared__ float red[DF];
    red[t] = fabsf(v1 - v2);
    __syncthreads();
    for (int s = DF / 2; s > 0; s >>= 1) {
        if (t < s) red[t] += red[t + s];
        __syncthreads();
    }
    if (t == 0) g_D[a] = red[0] + MARGINF;
}

// ---------------------------------------------------------------------------
// Kernel 2: L1 distance matrix, GEMM-style smem tiling.
//   side 0: g_ga[0] (a1) vs out2 ;  side 1: g_ga[1] (a2) vs out1
//   CTA tile: TA x TN, thread tile: RA x RN, k-loop over DF in float4 chunks.
// ---------------------------------------------------------------------------
__global__ __launch_bounds__(256, 4) void k_dist(const float* __restrict__ out1,
                                                 const float* __restrict__ out2) {
    extern __shared__ float sm[];
    float* sA = sm;                 // TA rows, stride SROW
    float* sN = sm + TA * SROW;     // TN rows, stride SROW

    const int side = blockIdx.z;
    const int aT = blockIdx.y;
    const int nT = blockIdx.x;
    const float* nodes = side ? out1 : out2;
    const int tid = threadIdx.x;

    // stage anchor tile (contiguous in g_ga)
    const float4* asrc = (const float4*)&g_ga[side][aT * TA][0];
    for (int i = tid; i < TA * (DF / 4); i += 256) {
        int r = i >> 5, c = i & 31;
        *(float4*)&sA[r * SROW + c * 4] = asrc[i];
    }
    // stage node tile (contiguous block of node matrix)
    const float4* nsrc = (const float4*)(nodes + (size_t)nT * TN * DF);
    for (int i = tid; i < TN * (DF / 4); i += 256) {
        int r = i >> 5, c = i & 31;
        *(float4*)&sN[r * SROW + c * 4] = nsrc[i];
    }
    __syncthreads();

    const int ta = tid >> 5;   // 0..7  : anchor group (broadcast within warp)
    const int tn = tid & 31;   // 0..31 : node lane
    float acc[RA][RN];
#pragma unroll
    for (int i = 0; i < RA; i++)
#pragma unroll
        for (int j = 0; j < RN; j++) acc[i][j] = 0.f;

    const float* aB = &sA[(ta * RA) * SROW];
    const float* nB = &sN[tn * SROW];

#pragma unroll 2
    for (int k = 0; k < DF; k += 4) {
        float4 av[RA], nv[RN];
#pragma unroll
        for (int i = 0; i < RA; i++) av[i] = *(const float4*)&aB[i * SROW + k];
#pragma unroll
        for (int j = 0; j < RN; j++) nv[j] = *(const float4*)&nB[j * 32 * SROW + k];
#pragma unroll
        for (int i = 0; i < RA; i++)
#pragma unroll
            for (int j = 0; j < RN; j++) {
                float s = acc[i][j];
                s += fabsf(av[i].x - nv[j].x);
                s += fabsf(av[i].y - nv[j].y);
                s += fabsf(av[i].z - nv[j].z);
                s += fabsf(av[i].w - nv[j].w);
                acc[i][j] = s;
            }
    }

#pragma unroll
    for (int i = 0; i < RA; i++) {
        int A = aT * TA + ta * RA + i;
#pragma unroll
        for (int j = 0; j < RN; j++) {
            int n = nT * TN + tn + j * 32;
            g_dist[side][A][n] = acc[i][j];
        }
    }
}

// ---------------------------------------------------------------------------
// Kernel 3: per-row exact 32-smallest + relu-margin loss.
//   Prune: T0 = 32nd smallest of the 256 per-thread chunk minima is a proven
//   upper bound on the 32nd smallest global value -> candidates = {v <= T0},
//   at most ~32*32 = 1024 elements. Then 32 exact extract-min iterations.
//   Values extracted in ascending order -> deterministic sum; only values
//   matter (ties are benign for the loss).
// ---------------------------------------------------------------------------
__global__ __launch_bounds__(256) void k_topk() {
    const int row = blockIdx.x;                 // 0..1023
    const int side = row >> 9, a = row & (NA - 1);
    const float* __restrict__ drow = &g_dist[side][a][0];
    const int tid = threadIdx.x;

    __shared__ float smin[256];
    __shared__ float cand[2048];
    __shared__ unsigned long long wmin[8];
    __shared__ int scnt;
    __shared__ float T0s;

    float mv = 3.0e38f;
#pragma unroll 4
    for (int i = tid; i < NN; i += 256) mv = fminf(mv, drow[i]);
    smin[tid] = mv;
    if (tid == 0) scnt = 0;
    __syncthreads();

    // rank of my chunk-min among 256 (strict total order via index tiebreak)
    int rank = 0;
    for (int i = 0; i < 256; i++) {
        float o = smin[i];
        rank += (o < mv) || (o == mv && i < tid);
    }
    if (rank == KSEL - 1) T0s = mv;             // exactly one thread
    __syncthreads();
    const float T0 = T0s;

    // gather candidates <= T0 (guaranteed to contain the 32 smallest)
    for (int i = tid; i < NN; i += 256) {
        float v = drow[i];
        if (v <= T0) {
            int p = atomicAdd(&scnt, 1);
            if (p < 2048) cand[p] = v;          // only drops exact-tie values
        }
    }
    __syncthreads();
    const int cnt = min(scnt, 2048);

    const float Dv = g_D[a];
    float loss = 0.f;
    for (int it = 0; it < KSEL; it++) {
        unsigned long long key = 0xFFFFFFFFFFFFFFFFull;
        for (int i = tid; i < cnt; i += 256) {
            // positive floats: uint bits are order-preserving
            unsigned long long k2 =
                ((unsigned long long)__float_as_uint(cand[i]) << 32) | (unsigned)i;
            key = (k2 < key) ? k2 : key;
        }
#pragma unroll
        for (int o = 16; o; o >>= 1) {
            unsigned long long other = __shfl_xor_sync(0xffffffffu, key, o);
            key = (other < key) ? other : key;
        }
        if ((tid & 31) == 0) wmin[tid >> 5] = key;
        __syncthreads();
        if (tid == 0) {
            unsigned long long best = wmin[0];
            for (int w = 1; w < 8; w++) best = (wmin[w] < best) ? wmin[w] : best;
            float v = __uint_as_float((unsigned)(best >> 32));
            int idx = (int)(best & 0xffffffffu);
            cand[idx] = 3.0e38f;                // remove
            loss += fmaxf(Dv - v, 0.f);         // relu(D + (-d))
        }
        __syncthreads();
    }
    if (tid == 0) g_rowLoss[row] = loss;
}

// ---------------------------------------------------------------------------
// Kernel 4: deterministic final reduction + normalization
// ---------------------------------------------------------------------------
__global__ void k_final(float* __restrict__ out) {
    __shared__ float red[256];
    int t = threadIdx.x;
    float s = g_rowLoss[t] + g_rowLoss[t + 256] + g_rowLoss[t + 512] + g_rowLoss[t + 768];
    red[t] = s;
    __syncthreads();
    for (int x = 128; x > 0; x >>= 1) {
        if (t < x) red[t] += red[t + x];
        __syncthreads();
    }
    if (t == 0) out[0] = red[0] / (float)(NA * KSEL);
}

// ---------------------------------------------------------------------------
extern "C" void kernel_launch(void* const* d_in, const int* in_sizes, int n_in,
                              void* d_out, int out_size) {
    const float* out1 = (const float*)d_in[0];
    const float* out2 = (const float*)d_in[1];
    const int* an1 = (const int*)d_in[2];
    const int* an2 = (const int*)d_in[3];
    float* out = (float*)d_out;

    const int smem = (TA + TN) * SROW * (int)sizeof(float);  // 50688 B
    cudaFuncSetAttribute(k_dist, cudaFuncAttributeMaxDynamicSharedMemorySize, smem);

    k_gather<<<NA, DF>>>(out1, out2, an1, an2);
    dim3 g(NN / TN, NA / TA, 2);
    k_dist<<<g, 256, smem>>>(out1, out2);
    k_topk<<<2 * NA, 256>>>();
    k_final<<<1, 256>>>(out);
}